// round 1
// baseline (speedup 1.0000x reference)
#include <cuda_runtime.h>
#include <math.h>

#define BN 8192
#define DN 384
#define RN 8
#define HN 64
#define EN 1024
#define GATE_BLOCKS (BN/8)

// ---------------- scratch (static device globals; no allocation) ----------------
__device__ float g_xu[BN*2*HN];        // 4 MB  : normalized x@Uw rows, indexed by pair id (2b+k)
__device__ float g_scores[BN*2*EN];    // 64 MB : score rows per pair
__device__ float g_ev[RN*EN*HN];       // 2 MB  : normalized re@Vw
__device__ int   g_topidx[BN*2];
__device__ float g_topw[BN*2];
__device__ int   g_cnt[RN];
__device__ int   g_list[RN*BN];        // per-router pair lists
__device__ float g_auxp[GATE_BLOCKS*16];

// ---------------- init ----------------
__global__ void init_kernel() {
    int t = threadIdx.x;
    if (t < RN) g_cnt[t] = 0;
}

// ---------------- gate: logits, softmax, top-2, lists, aux partials ----------------
__global__ __launch_bounds__(256) void gate_kernel(const float* __restrict__ x,
                                                   const float* __restrict__ gw,
                                                   const float* __restrict__ gb) {
    __shared__ float warpAux[8][16];
    int tid = threadIdx.x;
    int warp = tid >> 5, lane = tid & 31;
    int b = blockIdx.x * 8 + warp;

    float acc[RN];
#pragma unroll
    for (int r = 0; r < RN; r++) acc[r] = 0.f;
    const float* xb = x + b * DN;
#pragma unroll 4
    for (int i = 0; i < DN / 32; i++) {
        int d = lane + 32 * i;
        float xv = xb[d];
        const float4* g4 = reinterpret_cast<const float4*>(gw + d * RN);
        float4 w0 = g4[0], w1 = g4[1];
        acc[0] += xv * w0.x; acc[1] += xv * w0.y; acc[2] += xv * w0.z; acc[3] += xv * w0.w;
        acc[4] += xv * w1.x; acc[5] += xv * w1.y; acc[6] += xv * w1.z; acc[7] += xv * w1.w;
    }
#pragma unroll
    for (int r = 0; r < RN; r++) {
#pragma unroll
        for (int off = 16; off > 0; off >>= 1)
            acc[r] += __shfl_down_sync(0xffffffffu, acc[r], off);
    }

    if (lane == 0) {
        float lg[RN]; float m = -3.4e38f;
#pragma unroll
        for (int r = 0; r < RN; r++) { lg[r] = acc[r] + gb[r]; m = fmaxf(m, lg[r]); }
        float Z = 0.f; float pr[RN];
#pragma unroll
        for (int r = 0; r < RN; r++) { pr[r] = __expf(lg[r] - m); Z += pr[r]; }
        float invZ = 1.f / Z;

        // top-2 (strict > keeps lowest index on ties, matching lax.top_k)
        int i0 = 0; float v0 = lg[0];
        int i1 = -1; float v1 = -3.4e38f;
#pragma unroll
        for (int r = 1; r < RN; r++) {
            if (lg[r] > v0) { i1 = i0; v1 = v0; i0 = r; v0 = lg[r]; }
            else if (lg[r] > v1) { i1 = r; v1 = lg[r]; }
        }
        float e1 = __expf(v1 - v0);
        float w0 = 1.f / (1.f + e1);
        float w1 = e1 / (1.f + e1);

        g_topidx[2*b]   = i0;  g_topidx[2*b+1] = i1;
        g_topw[2*b]     = w0;  g_topw[2*b+1]   = w1;
        int s0 = atomicAdd(&g_cnt[i0], 1);  g_list[i0*BN + s0] = 2*b;
        int s1 = atomicAdd(&g_cnt[i1], 1);  g_list[i1*BN + s1] = 2*b + 1;

#pragma unroll
        for (int r = 0; r < RN; r++) {
            warpAux[warp][r]     = pr[r] * invZ;
            warpAux[warp][8 + r] = (r == i0 || r == i1) ? 1.f : 0.f;
        }
    }
    __syncthreads();
    if (tid < 16) {
        float s = 0.f;
        for (int w = 0; w < 8; w++) s += warpAux[w][tid];
        g_auxp[blockIdx.x * 16 + tid] = s;
    }
}

// ---------------- ev: normalized re @ Vw + Vb ----------------
__global__ __launch_bounds__(256) void ev_kernel(const float* __restrict__ re,
                                                 const float* __restrict__ Vw,
                                                 const float* __restrict__ Vb) {
    __shared__ float xs[16][DN];
    __shared__ float us[16][HN];
    __shared__ float inv[16];
    int r = blockIdx.x;
    int e0 = blockIdx.y * 16;
    int tid = threadIdx.x;

    for (int idx = tid; idx < 16 * DN; idx += 256) {
        int row = idx / DN, d = idx % DN;
        xs[row][d] = re[(e0 + row) * DN + d];
    }
    __syncthreads();

    int h = tid & 63, q = tid >> 6;
    float a0 = 0.f, a1 = 0.f, a2 = 0.f, a3 = 0.f;
    const float* W = Vw + r * DN * HN + h;
#pragma unroll 4
    for (int d = 0; d < DN; d++) {
        float w = W[d * HN];
        a0 += w * xs[q][d];
        a1 += w * xs[q + 4][d];
        a2 += w * xs[q + 8][d];
        a3 += w * xs[q + 12][d];
    }
    float bb = Vb[r * HN + h];
    us[q][h] = a0 + bb; us[q+4][h] = a1 + bb; us[q+8][h] = a2 + bb; us[q+12][h] = a3 + bb;
    __syncthreads();

    int warp = tid >> 5, lane = tid & 31;
#pragma unroll
    for (int rr = warp * 2; rr < warp * 2 + 2; rr++) {
        float v = us[rr][lane] * us[rr][lane] + us[rr][lane + 32] * us[rr][lane + 32];
#pragma unroll
        for (int off = 16; off > 0; off >>= 1) v += __shfl_down_sync(0xffffffffu, v, off);
        if (lane == 0) inv[rr] = 1.f / fmaxf(sqrtf(v), 1e-12f);
    }
    __syncthreads();
#pragma unroll
    for (int j = 0; j < 4; j++) {
        int row = q + 4 * j;
        g_ev[(r * EN + e0 + row) * HN + h] = us[row][h] * inv[row];
    }
}

// ---------------- xu: normalized x @ Uw + Ub for selected pairs (router-grouped) ----------------
__global__ __launch_bounds__(256) void xu_kernel(const float* __restrict__ x,
                                                 const float* __restrict__ Uw,
                                                 const float* __restrict__ Ub) {
    __shared__ float xs[16][DN];
    __shared__ float us[16][HN];
    __shared__ float inv[16];
    __shared__ int pairS[16];
    int r = blockIdx.x;
    int n = g_cnt[r];
    int t0 = blockIdx.y * 16;
    if (t0 >= n) return;
    int rows = min(16, n - t0);
    int tid = threadIdx.x;

    if (tid < 16) pairS[tid] = (tid < rows) ? g_list[r * BN + t0 + tid] : g_list[r * BN + t0];
    __syncthreads();
    for (int idx = tid; idx < 16 * DN; idx += 256) {
        int row = idx / DN, d = idx % DN;
        int b = pairS[row] >> 1;
        xs[row][d] = x[b * DN + d];
    }
    __syncthreads();

    int h = tid & 63, q = tid >> 6;
    float a0 = 0.f, a1 = 0.f, a2 = 0.f, a3 = 0.f;
    const float* W = Uw + r * DN * HN + h;
#pragma unroll 4
    for (int d = 0; d < DN; d++) {
        float w = W[d * HN];
        a0 += w * xs[q][d];
        a1 += w * xs[q + 4][d];
        a2 += w * xs[q + 8][d];
        a3 += w * xs[q + 12][d];
    }
    float bb = Ub[r * HN + h];
    us[q][h] = a0 + bb; us[q+4][h] = a1 + bb; us[q+8][h] = a2 + bb; us[q+12][h] = a3 + bb;
    __syncthreads();

    int warp = tid >> 5, lane = tid & 31;
#pragma unroll
    for (int rr = warp * 2; rr < warp * 2 + 2; rr++) {
        float v = us[rr][lane] * us[rr][lane] + us[rr][lane + 32] * us[rr][lane + 32];
#pragma unroll
        for (int off = 16; off > 0; off >>= 1) v += __shfl_down_sync(0xffffffffu, v, off);
        if (lane == 0) inv[rr] = 1.f / fmaxf(sqrtf(v), 1e-12f);
    }
    __syncthreads();
#pragma unroll
    for (int j = 0; j < 4; j++) {
        int row = q + 4 * j;
        if (row < rows)
            g_xu[pairS[row] * HN + h] = us[row][h] * inv[row];
    }
}

// ---------------- score GEMM: per router, Xu[n_r,64] @ ev_r^T[64,1024] ----------------
// 64-row x 128-col tile per block, K=64. smem exactly 48KB; B tile XOR-swizzled.
__global__ __launch_bounds__(256) void score_kernel() {
    __shared__ float As[64 * 64];
    __shared__ float Bs[128 * 64];
    int r = blockIdx.x;
    int n = g_cnt[r];
    int row0 = blockIdx.y * 64;
    if (row0 >= n) return;
    int nrows = min(64, n - row0);
    int tid = threadIdx.x;

    for (int idx = tid; idx < 64 * HN; idx += 256) {
        int row = idx >> 6, h = idx & 63;
        int pid = (row < nrows) ? g_list[r * BN + row0 + row] : 0;
        As[row * 64 + h] = (row < nrows) ? g_xu[pid * HN + h] : 0.f;
    }

    int tr = tid >> 4, tc = tid & 15;
    for (int ct = 0; ct < 8; ct++) {
        int c0 = ct * 128;
        __syncthreads();
        for (int idx = tid; idx < 128 * HN; idx += 256) {
            int e = idx >> 6, h = idx & 63;
            Bs[e * 64 + (h ^ (e & 31))] = g_ev[(r * EN + c0 + e) * HN + h];
        }
        __syncthreads();

        float acc[4][8];
#pragma unroll
        for (int i = 0; i < 4; i++)
#pragma unroll
            for (int j = 0; j < 8; j++) acc[i][j] = 0.f;

#pragma unroll 8
        for (int kk = 0; kk < HN; kk++) {
            float a[4], bv[8];
#pragma unroll
            for (int i = 0; i < 4; i++) a[i] = As[(tr + 16 * i) * 64 + kk];
#pragma unroll
            for (int j = 0; j < 8; j++) {
                int c = tc + 16 * j;
                bv[j] = Bs[c * 64 + (kk ^ (c & 31))];
            }
#pragma unroll
            for (int i = 0; i < 4; i++)
#pragma unroll
                for (int j = 0; j < 8; j++) acc[i][j] += a[i] * bv[j];
        }

#pragma unroll
        for (int i = 0; i < 4; i++) {
            int row = tr + 16 * i;
            if (row < nrows) {
                int pid = g_list[r * BN + row0 + row];
                float* dst = g_scores + pid * EN + c0;
#pragma unroll
                for (int j = 0; j < 8; j++) dst[tc + 16 * j] = acc[i][j];
            }
        }
    }
}

// ---------------- sample: dual softmax + combine + scan + inverse-CDF + log ----------------
__global__ __launch_bounds__(256) void sample_kernel(const float* __restrict__ rnd,
                                                     float* __restrict__ out) {
    __shared__ float s0[EN];
    __shared__ float s1[EN];
    __shared__ float rea[EN];
    __shared__ float cum[EN];
    __shared__ float sred[8];
    __shared__ float st[4];
    __shared__ int selS;
    int b = blockIdx.x;
    int tid = threadIdx.x;
    int lane = tid & 31, warp = tid >> 5;

    const float* p0 = g_scores + (2 * b) * EN;
    const float* p1 = g_scores + (2 * b + 1) * EN;
#pragma unroll
    for (int i = 0; i < 4; i++) { int e = tid + 256 * i; s0[e] = p0[e]; s1[e] = p1[e]; }
    __syncthreads();

    // m0
    float v = -3.4e38f;
#pragma unroll
    for (int i = 0; i < 4; i++) v = fmaxf(v, s0[tid + 256 * i]);
#pragma unroll
    for (int off = 16; off > 0; off >>= 1) v = fmaxf(v, __shfl_down_sync(0xffffffffu, v, off));
    if (lane == 0) sred[warp] = v;
    __syncthreads();
    if (tid == 0) { float m = sred[0]; for (int w = 1; w < 8; w++) m = fmaxf(m, sred[w]); st[0] = m; }
    __syncthreads();
    float m0 = st[0];

    // Z0
    v = 0.f;
#pragma unroll
    for (int i = 0; i < 4; i++) v += __expf(s0[tid + 256 * i] - m0);
#pragma unroll
    for (int off = 16; off > 0; off >>= 1) v += __shfl_down_sync(0xffffffffu, v, off);
    if (lane == 0) sred[warp] = v;
    __syncthreads();
    if (tid == 0) { float s = 0.f; for (int w = 0; w < 8; w++) s += sred[w]; st[1] = s; }
    __syncthreads();
    float Z0 = st[1];

    // m1
    v = -3.4e38f;
#pragma unroll
    for (int i = 0; i < 4; i++) v = fmaxf(v, s1[tid + 256 * i]);
#pragma unroll
    for (int off = 16; off > 0; off >>= 1) v = fmaxf(v, __shfl_down_sync(0xffffffffu, v, off));
    if (lane == 0) sred[warp] = v;
    __syncthreads();
    if (tid == 0) { float m = sred[0]; for (int w = 1; w < 8; w++) m = fmaxf(m, sred[w]); st[2] = m; }
    __syncthreads();
    float m1 = st[2];

    // Z1
    v = 0.f;
#pragma unroll
    for (int i = 0; i < 4; i++) v += __expf(s1[tid + 256 * i] - m1);
#pragma unroll
    for (int off = 16; off > 0; off >>= 1) v += __shfl_down_sync(0xffffffffu, v, off);
    if (lane == 0) sred[warp] = v;
    __syncthreads();
    if (tid == 0) { float s = 0.f; for (int w = 0; w < 8; w++) s += sred[w]; st[3] = s; }
    __syncthreads();
    float Z1 = st[3];

    float w0 = g_topw[2 * b], w1 = g_topw[2 * b + 1];
    float c0 = w0 / Z0, c1 = w1 / Z1;
#pragma unroll
    for (int i = 0; i < 4; i++) {
        int e = tid + 256 * i;
        rea[e] = c0 * __expf(s0[e] - m0) + c1 * __expf(s1[e] - m1);
    }
    __syncthreads();

    // block-wide inclusive scan, thread owns rea[4t..4t+3]
    float l0 = rea[4 * tid], l1 = rea[4 * tid + 1], l2 = rea[4 * tid + 2], l3 = rea[4 * tid + 3];
    float q0 = l0, q1 = q0 + l1, q2 = q1 + l2, q3 = q2 + l3;
    float t = q3, vsc = t;
#pragma unroll
    for (int off = 1; off < 32; off <<= 1) {
        float u = __shfl_up_sync(0xffffffffu, vsc, off);
        if (lane >= off) vsc += u;
    }
    if (lane == 31) sred[warp] = vsc;
    __syncthreads();
    if (warp == 0) {
        float w = (lane < 8) ? sred[lane] : 0.f;
#pragma unroll
        for (int off = 1; off < 8; off <<= 1) {
            float u = __shfl_up_sync(0xffffffffu, w, off);
            if (lane >= off) w += u;
        }
        if (lane < 8) sred[lane] = w;
    }
    if (tid == 0) selS = EN;
    __syncthreads();
    float base = (warp ? sred[warp - 1] : 0.f) + (vsc - t);
    cum[4 * tid]     = base + q0;
    cum[4 * tid + 1] = base + q1;
    cum[4 * tid + 2] = base + q2;
    cum[4 * tid + 3] = base + q3;
    __syncthreads();

    float rv = rnd[b];
    int cand = EN;
#pragma unroll
    for (int i = 0; i < 4; i++) {
        int e = 4 * tid + i;
        if (cum[e] > rv) { cand = e; break; }
    }
    if (cand < EN) atomicMin(&selS, cand);
    __syncthreads();
    if (tid == 0) {
        int sel = (selS == EN) ? 0 : selS;
        out[b] = (float)sel;
        out[BN + b] = logf(rea[sel]);
    }
}

// ---------------- finish: deterministic aux loss ----------------
__global__ void finish_kernel(float* __restrict__ out) {
    __shared__ float col[16];
    int tid = threadIdx.x;
    if (tid < 16) {
        float s = 0.f;
        for (int bk = 0; bk < GATE_BLOCKS; bk++) s += g_auxp[bk * 16 + tid];
        col[tid] = s;
    }
    __syncthreads();
    if (tid == 0) {
        float s = 0.f;
        for (int r = 0; r < RN; r++) s += (col[r] / (float)BN) * (col[8 + r] / (float)BN);
        out[2 * BN] = (float)RN * s * 0.05f;
    }
}

// ---------------- launch ----------------
extern "C" void kernel_launch(void* const* d_in, const int* in_sizes, int n_in,
                              void* d_out, int out_size) {
    const float* x   = (const float*)d_in[0];
    const float* re  = (const float*)d_in[1];
    const float* rnd = (const float*)d_in[2];
    const float* gw  = (const float*)d_in[3];
    const float* gb  = (const float*)d_in[4];
    const float* Uw  = (const float*)d_in[5];
    const float* Ub  = (const float*)d_in[6];
    const float* Vw  = (const float*)d_in[7];
    const float* Vb  = (const float*)d_in[8];
    float* out = (float*)d_out;

    init_kernel<<<1, 32>>>();
    gate_kernel<<<GATE_BLOCKS, 256>>>(x, gw, gb);
    ev_kernel<<<dim3(RN, EN / 16), 256>>>(re, Vw, Vb);
    xu_kernel<<<dim3(RN, BN / 16), 256>>>(x, Uw, Ub);
    score_kernel<<<dim3(RN, BN / 64), 256>>>();
    sample_kernel<<<BN, 256>>>(rnd, out);
    finish_kernel<<<1, 32>>>(out);
}

// round 2
// speedup vs baseline: 1.0014x; 1.0014x over previous
#include <cuda_runtime.h>
#include <math.h>

#define BN 8192
#define DN 384
#define RN 8
#define HN 64
#define EN 1024
#define GATE_BLOCKS (BN/8)

// ---------------- scratch (static device globals; no allocation) ----------------
__device__ float g_xu[BN*2*HN];        // 4 MB  : normalized x@Uw rows, indexed by pair id (2b+k)
__device__ float g_scores[BN*2*EN];    // 64 MB : score rows per pair
__device__ float g_ev[RN*EN*HN];       // 2 MB  : normalized re@Vw
__device__ int   g_topidx[BN*2];
__device__ float g_topw[BN*2];
__device__ int   g_cnt[RN];
__device__ int   g_list[RN*BN];        // per-router pair lists
__device__ float g_auxp[GATE_BLOCKS*16];

// ---------------- init ----------------
__global__ void init_kernel() {
    int t = threadIdx.x;
    if (t < RN) g_cnt[t] = 0;
}

// ---------------- gate: logits, softmax, top-2, lists, aux partials ----------------
__global__ __launch_bounds__(256) void gate_kernel(const float* __restrict__ x,
                                                   const float* __restrict__ gw,
                                                   const float* __restrict__ gb) {
    __shared__ float warpAux[8][16];
    int tid = threadIdx.x;
    int warp = tid >> 5, lane = tid & 31;
    int b = blockIdx.x * 8 + warp;

    float acc[RN];
#pragma unroll
    for (int r = 0; r < RN; r++) acc[r] = 0.f;
    const float* xb = x + b * DN;
#pragma unroll 4
    for (int i = 0; i < DN / 32; i++) {
        int d = lane + 32 * i;
        float xv = xb[d];
        const float4* g4 = reinterpret_cast<const float4*>(gw + d * RN);
        float4 w0 = g4[0], w1 = g4[1];
        acc[0] += xv * w0.x; acc[1] += xv * w0.y; acc[2] += xv * w0.z; acc[3] += xv * w0.w;
        acc[4] += xv * w1.x; acc[5] += xv * w1.y; acc[6] += xv * w1.z; acc[7] += xv * w1.w;
    }
#pragma unroll
    for (int r = 0; r < RN; r++) {
#pragma unroll
        for (int off = 16; off > 0; off >>= 1)
            acc[r] += __shfl_down_sync(0xffffffffu, acc[r], off);
    }

    if (lane == 0) {
        float lg[RN]; float m = -3.4e38f;
#pragma unroll
        for (int r = 0; r < RN; r++) { lg[r] = acc[r] + gb[r]; m = fmaxf(m, lg[r]); }
        float Z = 0.f; float pr[RN];
#pragma unroll
        for (int r = 0; r < RN; r++) { pr[r] = __expf(lg[r] - m); Z += pr[r]; }
        float invZ = 1.f / Z;

        // top-2 (strict > keeps lowest index on ties, matching lax.top_k)
        int i0 = 0; float v0 = lg[0];
        int i1 = -1; float v1 = -3.4e38f;
#pragma unroll
        for (int r = 1; r < RN; r++) {
            if (lg[r] > v0) { i1 = i0; v1 = v0; i0 = r; v0 = lg[r]; }
            else if (lg[r] > v1) { i1 = r; v1 = lg[r]; }
        }
        float e1 = __expf(v1 - v0);
        float w0 = 1.f / (1.f + e1);
        float w1 = e1 / (1.f + e1);

        g_topidx[2*b]   = i0;  g_topidx[2*b+1] = i1;
        g_topw[2*b]     = w0;  g_topw[2*b+1]   = w1;
        int s0 = atomicAdd(&g_cnt[i0], 1);  g_list[i0*BN + s0] = 2*b;
        int s1 = atomicAdd(&g_cnt[i1], 1);  g_list[i1*BN + s1] = 2*b + 1;

#pragma unroll
        for (int r = 0; r < RN; r++) {
            warpAux[warp][r]     = pr[r] * invZ;
            warpAux[warp][8 + r] = (r == i0 || r == i1) ? 1.f : 0.f;
        }
    }
    __syncthreads();
    if (tid < 16) {
        float s = 0.f;
        for (int w = 0; w < 8; w++) s += warpAux[w][tid];
        g_auxp[blockIdx.x * 16 + tid] = s;
    }
}

// ---------------- ev: normalized re @ Vw + Vb ----------------
__global__ __launch_bounds__(256) void ev_kernel(const float* __restrict__ re,
                                                 const float* __restrict__ Vw,
                                                 const float* __restrict__ Vb) {
    __shared__ float xs[16][DN];
    __shared__ float us[16][HN];
    __shared__ float inv[16];
    int r = blockIdx.x;
    int e0 = blockIdx.y * 16;
    int tid = threadIdx.x;

    for (int idx = tid; idx < 16 * DN; idx += 256) {
        int row = idx / DN, d = idx % DN;
        xs[row][d] = re[(e0 + row) * DN + d];
    }
    __syncthreads();

    int h = tid & 63, q = tid >> 6;
    float a0 = 0.f, a1 = 0.f, a2 = 0.f, a3 = 0.f;
    const float* W = Vw + r * DN * HN + h;
#pragma unroll 4
    for (int d = 0; d < DN; d++) {
        float w = W[d * HN];
        a0 += w * xs[q][d];
        a1 += w * xs[q + 4][d];
        a2 += w * xs[q + 8][d];
        a3 += w * xs[q + 12][d];
    }
    float bb = Vb[r * HN + h];
    us[q][h] = a0 + bb; us[q+4][h] = a1 + bb; us[q+8][h] = a2 + bb; us[q+12][h] = a3 + bb;
    __syncthreads();

    int warp = tid >> 5, lane = tid & 31;
#pragma unroll
    for (int rr = warp * 2; rr < warp * 2 + 2; rr++) {
        float v = us[rr][lane] * us[rr][lane] + us[rr][lane + 32] * us[rr][lane + 32];
#pragma unroll
        for (int off = 16; off > 0; off >>= 1) v += __shfl_down_sync(0xffffffffu, v, off);
        if (lane == 0) inv[rr] = 1.f / fmaxf(sqrtf(v), 1e-12f);
    }
    __syncthreads();
#pragma unroll
    for (int j = 0; j < 4; j++) {
        int row = q + 4 * j;
        g_ev[(r * EN + e0 + row) * HN + h] = us[row][h] * inv[row];
    }
}

// ---------------- xu: normalized x @ Uw + Ub for selected pairs (router-grouped) ----------------
__global__ __launch_bounds__(256) void xu_kernel(const float* __restrict__ x,
                                                 const float* __restrict__ Uw,
                                                 const float* __restrict__ Ub) {
    __shared__ float xs[16][DN];
    __shared__ float us[16][HN];
    __shared__ float inv[16];
    __shared__ int pairS[16];
    int r = blockIdx.x;
    int n = g_cnt[r];
    int t0 = blockIdx.y * 16;
    if (t0 >= n) return;
    int rows = min(16, n - t0);
    int tid = threadIdx.x;

    if (tid < 16) pairS[tid] = (tid < rows) ? g_list[r * BN + t0 + tid] : g_list[r * BN + t0];
    __syncthreads();
    for (int idx = tid; idx < 16 * DN; idx += 256) {
        int row = idx / DN, d = idx % DN;
        int b = pairS[row] >> 1;
        xs[row][d] = x[b * DN + d];
    }
    __syncthreads();

    int h = tid & 63, q = tid >> 6;
    float a0 = 0.f, a1 = 0.f, a2 = 0.f, a3 = 0.f;
    const float* W = Uw + r * DN * HN + h;
#pragma unroll 4
    for (int d = 0; d < DN; d++) {
        float w = W[d * HN];
        a0 += w * xs[q][d];
        a1 += w * xs[q + 4][d];
        a2 += w * xs[q + 8][d];
        a3 += w * xs[q + 12][d];
    }
    float bb = Ub[r * HN + h];
    us[q][h] = a0 + bb; us[q+4][h] = a1 + bb; us[q+8][h] = a2 + bb; us[q+12][h] = a3 + bb;
    __syncthreads();

    int warp = tid >> 5, lane = tid & 31;
#pragma unroll
    for (int rr = warp * 2; rr < warp * 2 + 2; rr++) {
        float v = us[rr][lane] * us[rr][lane] + us[rr][lane + 32] * us[rr][lane + 32];
#pragma unroll
        for (int off = 16; off > 0; off >>= 1) v += __shfl_down_sync(0xffffffffu, v, off);
        if (lane == 0) inv[rr] = 1.f / fmaxf(sqrtf(v), 1e-12f);
    }
    __syncthreads();
#pragma unroll
    for (int j = 0; j < 4; j++) {
        int row = q + 4 * j;
        if (row < rows)
            g_xu[pairS[row] * HN + h] = us[row][h] * inv[row];
    }
}

// ---------------- score GEMM: per router, Xu[n_r,64] @ ev_r^T[64,1024] ----------------
// 64-row x 128-col tile per block, K=64. smem exactly 48KB; B tile XOR-swizzled.
__global__ __launch_bounds__(256) void score_kernel() {
    __shared__ float As[64 * 64];
    __shared__ float Bs[128 * 64];
    int r = blockIdx.x;
    int n = g_cnt[r];
    int row0 = blockIdx.y * 64;
    if (row0 >= n) return;
    int nrows = min(64, n - row0);
    int tid = threadIdx.x;

    for (int idx = tid; idx < 64 * HN; idx += 256) {
        int row = idx >> 6, h = idx & 63;
        int pid = (row < nrows) ? g_list[r * BN + row0 + row] : 0;
        As[row * 64 + h] = (row < nrows) ? g_xu[pid * HN + h] : 0.f;
    }

    int tr = tid >> 4, tc = tid & 15;
    for (int ct = 0; ct < 8; ct++) {
        int c0 = ct * 128;
        __syncthreads();
        for (int idx = tid; idx < 128 * HN; idx += 256) {
            int e = idx >> 6, h = idx & 63;
            Bs[e * 64 + (h ^ (e & 31))] = g_ev[(r * EN + c0 + e) * HN + h];
        }
        __syncthreads();

        float acc[4][8];
#pragma unroll
        for (int i = 0; i < 4; i++)
#pragma unroll
            for (int j = 0; j < 8; j++) acc[i][j] = 0.f;

#pragma unroll 8
        for (int kk = 0; kk < HN; kk++) {
            float a[4], bv[8];
#pragma unroll
            for (int i = 0; i < 4; i++) a[i] = As[(tr + 16 * i) * 64 + kk];
#pragma unroll
            for (int j = 0; j < 8; j++) {
                int c = tc + 16 * j;
                bv[j] = Bs[c * 64 + (kk ^ (c & 31))];
            }
#pragma unroll
            for (int i = 0; i < 4; i++)
#pragma unroll
                for (int j = 0; j < 8; j++) acc[i][j] += a[i] * bv[j];
        }

#pragma unroll
        for (int i = 0; i < 4; i++) {
            int row = tr + 16 * i;
            if (row < nrows) {
                int pid = g_list[r * BN + row0 + row];
                float* dst = g_scores + pid * EN + c0;
#pragma unroll
                for (int j = 0; j < 8; j++) dst[tc + 16 * j] = acc[i][j];
            }
        }
    }
}

// ---------------- sample: dual softmax + combine + scan + inverse-CDF + log ----------------
__global__ __launch_bounds__(256) void sample_kernel(const float* __restrict__ rnd,
                                                     float* __restrict__ out) {
    __shared__ float s0[EN];
    __shared__ float s1[EN];
    __shared__ float rea[EN];
    __shared__ float cum[EN];
    __shared__ float sred[8];
    __shared__ float st[4];
    __shared__ int selS;
    int b = blockIdx.x;
    int tid = threadIdx.x;
    int lane = tid & 31, warp = tid >> 5;

    const float* p0 = g_scores + (2 * b) * EN;
    const float* p1 = g_scores + (2 * b + 1) * EN;
#pragma unroll
    for (int i = 0; i < 4; i++) { int e = tid + 256 * i; s0[e] = p0[e]; s1[e] = p1[e]; }
    __syncthreads();

    // m0
    float v = -3.4e38f;
#pragma unroll
    for (int i = 0; i < 4; i++) v = fmaxf(v, s0[tid + 256 * i]);
#pragma unroll
    for (int off = 16; off > 0; off >>= 1) v = fmaxf(v, __shfl_down_sync(0xffffffffu, v, off));
    if (lane == 0) sred[warp] = v;
    __syncthreads();
    if (tid == 0) { float m = sred[0]; for (int w = 1; w < 8; w++) m = fmaxf(m, sred[w]); st[0] = m; }
    __syncthreads();
    float m0 = st[0];

    // Z0
    v = 0.f;
#pragma unroll
    for (int i = 0; i < 4; i++) v += __expf(s0[tid + 256 * i] - m0);
#pragma unroll
    for (int off = 16; off > 0; off >>= 1) v += __shfl_down_sync(0xffffffffu, v, off);
    if (lane == 0) sred[warp] = v;
    __syncthreads();
    if (tid == 0) { float s = 0.f; for (int w = 0; w < 8; w++) s += sred[w]; st[1] = s; }
    __syncthreads();
    float Z0 = st[1];

    // m1
    v = -3.4e38f;
#pragma unroll
    for (int i = 0; i < 4; i++) v = fmaxf(v, s1[tid + 256 * i]);
#pragma unroll
    for (int off = 16; off > 0; off >>= 1) v = fmaxf(v, __shfl_down_sync(0xffffffffu, v, off));
    if (lane == 0) sred[warp] = v;
    __syncthreads();
    if (tid == 0) { float m = sred[0]; for (int w = 1; w < 8; w++) m = fmaxf(m, sred[w]); st[2] = m; }
    __syncthreads();
    float m1 = st[2];

    // Z1
    v = 0.f;
#pragma unroll
    for (int i = 0; i < 4; i++) v += __expf(s1[tid + 256 * i] - m1);
#pragma unroll
    for (int off = 16; off > 0; off >>= 1) v += __shfl_down_sync(0xffffffffu, v, off);
    if (lane == 0) sred[warp] = v;
    __syncthreads();
    if (tid == 0) { float s = 0.f; for (int w = 0; w < 8; w++) s += sred[w]; st[3] = s; }
    __syncthreads();
    float Z1 = st[3];

    float w0 = g_topw[2 * b], w1 = g_topw[2 * b + 1];
    float c0 = w0 / Z0, c1 = w1 / Z1;
#pragma unroll
    for (int i = 0; i < 4; i++) {
        int e = tid + 256 * i;
        rea[e] = c0 * __expf(s0[e] - m0) + c1 * __expf(s1[e] - m1);
    }
    __syncthreads();

    // block-wide inclusive scan, thread owns rea[4t..4t+3]
    float l0 = rea[4 * tid], l1 = rea[4 * tid + 1], l2 = rea[4 * tid + 2], l3 = rea[4 * tid + 3];
    float q0 = l0, q1 = q0 + l1, q2 = q1 + l2, q3 = q2 + l3;
    float t = q3, vsc = t;
#pragma unroll
    for (int off = 1; off < 32; off <<= 1) {
        float u = __shfl_up_sync(0xffffffffu, vsc, off);
        if (lane >= off) vsc += u;
    }
    if (lane == 31) sred[warp] = vsc;
    __syncthreads();
    if (warp == 0) {
        float w = (lane < 8) ? sred[lane] : 0.f;
#pragma unroll
        for (int off = 1; off < 8; off <<= 1) {
            float u = __shfl_up_sync(0xffffffffu, w, off);
            if (lane >= off) w += u;
        }
        if (lane < 8) sred[lane] = w;
    }
    if (tid == 0) selS = EN;
    __syncthreads();
    float base = (warp ? sred[warp - 1] : 0.f) + (vsc - t);
    cum[4 * tid]     = base + q0;
    cum[4 * tid + 1] = base + q1;
    cum[4 * tid + 2] = base + q2;
    cum[4 * tid + 3] = base + q3;
    __syncthreads();

    float rv = rnd[b];
    int cand = EN;
#pragma unroll
    for (int i = 0; i < 4; i++) {
        int e = 4 * tid + i;
        if (cum[e] > rv) { cand = e; break; }
    }
    if (cand < EN) atomicMin(&selS, cand);
    __syncthreads();
    if (tid == 0) {
        int sel = (selS == EN) ? 0 : selS;
        out[b] = (float)sel;
        out[BN + b] = logf(rea[sel]);
    }
}

// ---------------- finish: deterministic aux loss ----------------
__global__ void finish_kernel(float* __restrict__ out) {
    __shared__ float col[16];
    int tid = threadIdx.x;
    if (tid < 16) {
        float s = 0.f;
        for (int bk = 0; bk < GATE_BLOCKS; bk++) s += g_auxp[bk * 16 + tid];
        col[tid] = s;
    }
    __syncthreads();
    if (tid == 0) {
        float s = 0.f;
        for (int r = 0; r < RN; r++) s += (col[r] / (float)BN) * (col[8 + r] / (float)BN);
        out[2 * BN] = (float)RN * s * 0.05f;
    }
}

// ---------------- launch ----------------
extern "C" void kernel_launch(void* const* d_in, const int* in_sizes, int n_in,
                              void* d_out, int out_size) {
    const float* x   = (const float*)d_in[0];
    const float* re  = (const float*)d_in[1];
    const float* rnd = (const float*)d_in[2];
    const float* gw  = (const float*)d_in[3];
    const float* gb  = (const float*)d_in[4];
    const float* Uw  = (const float*)d_in[5];
    const float* Ub  = (const float*)d_in[6];
    const float* Vw  = (const float*)d_in[7];
    const float* Vb  = (const float*)d_in[8];
    float* out = (float*)d_out;

    init_kernel<<<1, 32>>>();
    gate_kernel<<<GATE_BLOCKS, 256>>>(x, gw, gb);
    ev_kernel<<<dim3(RN, EN / 16), 256>>>(re, Vw, Vb);
    xu_kernel<<<dim3(RN, BN / 16), 256>>>(x, Uw, Ub);
    score_kernel<<<dim3(RN, BN / 64), 256>>>();
    sample_kernel<<<BN, 256>>>(rnd, out);
    finish_kernel<<<1, 32>>>(out);
}

// round 4
// speedup vs baseline: 1.8726x; 1.8699x over previous
#include <cuda_runtime.h>
#include <math.h>

#define BN 8192
#define DN 384
#define RN 8
#define HN 64
#define EN 1024
#define GATE_BLOCKS (BN/8)
#define LCAP (2*BN)

__device__ float g_xu[2*BN*HN];
__device__ float g_scores[2*BN*EN];
__device__ float g_ev[RN*EN*HN];
__device__ float g_UwT[RN*HN*DN];
__device__ float g_VwT[RN*HN*DN];
__device__ float g_rowm[2*BN];
__device__ float g_topw[2*BN];
__device__ int   g_cnt[RN];
__device__ int   g_list[RN*LCAP];
__device__ float g_auxp[GATE_BLOCKS*16];

__device__ __forceinline__ unsigned long long ffma2(unsigned long long a,
                                                    unsigned long long b,
                                                    unsigned long long c) {
    unsigned long long d;
    asm("fma.rn.f32x2 %0,%1,%2,%3;" : "=l"(d) : "l"(a), "l"(b), "l"(c));
    return d;
}
__device__ __forceinline__ float psum(unsigned long long v) {
    float lo, hi;
    asm("mov.b64 {%0,%1},%2;" : "=f"(lo), "=f"(hi) : "l"(v));
    return lo + hi;
}

__global__ void init_kernel() {
    if (threadIdx.x < RN) g_cnt[threadIdx.x] = 0;
}

// transpose Uw/Vw -> [r][h][d]
__global__ __launch_bounds__(256) void prep_kernel(const float* __restrict__ Uw,
                                                   const float* __restrict__ Vw) {
    __shared__ float t[32][65];
    int r = blockIdx.x, m = blockIdx.y, d0 = blockIdx.z * 32, tid = threadIdx.x;
    const float* in = (m ? Vw : Uw) + r * DN * HN;
    float* outp = (m ? g_VwT : g_UwT) + r * HN * DN;
    for (int idx = tid; idx < 32 * 64; idx += 256) {
        int dd = idx >> 6, h = idx & 63;
        t[dd][h] = in[(d0 + dd) * HN + h];
    }
    __syncthreads();
    for (int idx = tid; idx < 64 * 32; idx += 256) {
        int h = idx >> 5, dd = idx & 31;
        outp[h * DN + d0 + dd] = t[dd][h];
    }
}

__global__ __launch_bounds__(256) void gate_kernel(const float* __restrict__ x,
                                                   const float* __restrict__ gw,
                                                   const float* __restrict__ gb) {
    __shared__ float warpAux[8][16];
    int tid = threadIdx.x, warp = tid >> 5, lane = tid & 31;
    int b = blockIdx.x * 8 + warp;
    float acc[RN];
#pragma unroll
    for (int r = 0; r < RN; r++) acc[r] = 0.f;
    const float* xb = x + b * DN;
#pragma unroll 4
    for (int i = 0; i < DN / 32; i++) {
        int d = lane + 32 * i;
        float xv = xb[d];
        const float4* g4 = reinterpret_cast<const float4*>(gw + d * RN);
        float4 w0 = g4[0], w1 = g4[1];
        acc[0] += xv * w0.x; acc[1] += xv * w0.y; acc[2] += xv * w0.z; acc[3] += xv * w0.w;
        acc[4] += xv * w1.x; acc[5] += xv * w1.y; acc[6] += xv * w1.z; acc[7] += xv * w1.w;
    }
#pragma unroll
    for (int r = 0; r < RN; r++)
#pragma unroll
        for (int off = 16; off > 0; off >>= 1)
            acc[r] += __shfl_down_sync(0xffffffffu, acc[r], off);

    if (lane == 0) {
        float lg[RN]; float m = -3.4e38f;
#pragma unroll
        for (int r = 0; r < RN; r++) { lg[r] = acc[r] + gb[r]; m = fmaxf(m, lg[r]); }
        float Z = 0.f, pr[RN];
#pragma unroll
        for (int r = 0; r < RN; r++) { pr[r] = __expf(lg[r] - m); Z += pr[r]; }
        float invZ = 1.f / Z;
        int i0 = 0; float v0 = lg[0];
        int i1 = -1; float v1 = -3.4e38f;
#pragma unroll
        for (int r = 1; r < RN; r++) {
            if (lg[r] > v0) { i1 = i0; v1 = v0; i0 = r; v0 = lg[r]; }
            else if (lg[r] > v1) { i1 = r; v1 = lg[r]; }
        }
        float e1 = __expf(v1 - v0);
        float w0 = 1.f / (1.f + e1), w1 = e1 / (1.f + e1);
        g_topw[2 * b] = w0; g_topw[2 * b + 1] = w1;
        int s0 = atomicAdd(&g_cnt[i0], 1); g_list[i0 * LCAP + s0] = 2 * b;
        int s1 = atomicAdd(&g_cnt[i1], 1); g_list[i1 * LCAP + s1] = 2 * b + 1;
#pragma unroll
        for (int r = 0; r < RN; r++) {
            warpAux[warp][r] = pr[r] * invZ;
            warpAux[warp][8 + r] = (r == i0 || r == i1) ? 1.f : 0.f;
        }
    }
    __syncthreads();
    if (tid < 16) {
        float s = 0.f;
        for (int w = 0; w < 8; w++) s += warpAux[w][tid];
        g_auxp[blockIdx.x * 16 + tid] = s;
    }
}

// proj GEMM: 64 rows x 64 cols, K=384, dot-product FFMA2 + l2norm.
// GATHER: rows from g_list (x@Uw -> g_xu); else identity rows (re@Vw -> g_ev).
template<bool GATHER>
__global__ __launch_bounds__(128) void proj_kernel(const float* __restrict__ X,
                                                   const float* __restrict__ bias) {
    __shared__ __align__(16) float As[64 * 32];
    __shared__ __align__(16) float Bs[64 * 32];
    __shared__ int pairS[64];
    int r = blockIdx.x, row0 = blockIdx.y * 64, tid = threadIdx.x;
    int nr = 64;
    if (GATHER) {
        int n = g_cnt[r];
        if (row0 >= n) return;
        nr = min(64, n - row0);
        if (tid < 64) pairS[tid] = g_list[r * LCAP + row0 + ((tid < nr) ? tid : 0)];
        __syncthreads();
    }
    int rg = tid >> 3, cg = tid & 7;
    const float* WT = (GATHER ? g_UwT : g_VwT) + r * HN * DN;

    unsigned long long acc[4][8];
#pragma unroll
    for (int i = 0; i < 4; i++)
#pragma unroll
        for (int j = 0; j < 8; j++) acc[i][j] = 0ull;

    for (int kt = 0; kt < DN / 32; kt++) {
        int k0 = kt * 32;
#pragma unroll
        for (int p = 0; p < 4; p++) {
            int idx = tid + 128 * p;
            int rr = idx >> 3, ku = idx & 7;
            const float* src = GATHER ? X + (pairS[rr] >> 1) * DN + k0 + 4 * ku
                                      : X + (row0 + rr) * DN + k0 + 4 * ku;
            *(float4*)(As + rr * 32 + 4 * ku) = *(const float4*)src;
        }
#pragma unroll
        for (int p = 0; p < 4; p++) {
            int idx = tid + 128 * p;
            int c = idx >> 3, ku = idx & 7;
            *(float4*)(Bs + c * 32 + 4 * (ku ^ (c >> 3))) =
                *(const float4*)(WT + c * DN + k0 + 4 * ku);
        }
        __syncthreads();
#pragma unroll
        for (int ks = 0; ks < 8; ks++) {
            ulonglong2 a2[4], b2[8];
#pragma unroll
            for (int i = 0; i < 4; i++)
                a2[i] = *(const ulonglong2*)(As + (4 * rg + i) * 32 + 4 * ks);
#pragma unroll
            for (int j = 0; j < 8; j++)
                b2[j] = *(const ulonglong2*)(Bs + (8 * cg + j) * 32 + 4 * (ks ^ cg));
#pragma unroll
            for (int i = 0; i < 4; i++)
#pragma unroll
                for (int j = 0; j < 8; j++) {
                    acc[i][j] = ffma2(a2[i].x, b2[j].x, acc[i][j]);
                    acc[i][j] = ffma2(a2[i].y, b2[j].y, acc[i][j]);
                }
        }
        __syncthreads();
    }
#pragma unroll
    for (int i = 0; i < 4; i++) {
        int row = 4 * rg + i;
        float vv[8]; float ssq = 0.f;
#pragma unroll
        for (int j = 0; j < 8; j++) {
            vv[j] = psum(acc[i][j]) + bias[r * HN + 8 * cg + j];
            ssq += vv[j] * vv[j];
        }
        ssq += __shfl_xor_sync(0xffffffffu, ssq, 1);
        ssq += __shfl_xor_sync(0xffffffffu, ssq, 2);
        ssq += __shfl_xor_sync(0xffffffffu, ssq, 4);
        float inv = 1.f / fmaxf(sqrtf(ssq), 1e-12f);
        float* dst;
        if (GATHER) {
            if (row >= nr) continue;
            dst = g_xu + pairS[row] * HN + 8 * cg;
        } else {
            dst = g_ev + (r * EN + row0 + row) * HN + 8 * cg;
        }
        *(float4*)dst = make_float4(vv[0] * inv, vv[1] * inv, vv[2] * inv, vv[3] * inv);
        *(float4*)(dst + 4) = make_float4(vv[4] * inv, vv[5] * inv, vv[6] * inv, vv[7] * inv);
    }
}

// score GEMM: 64 rows x 1024 cols, K=64, dot-product FFMA2, tracks row max.
__global__ __launch_bounds__(256) void score_kernel() {
    __shared__ __align__(16) float As[64 * 64];
    __shared__ __align__(16) float Bs[128 * 64];
    int r = blockIdx.x;
    int n = g_cnt[r];
    int row0 = blockIdx.y * 64;
    if (row0 >= n) return;
    int nr = min(64, n - row0);
    int tid = threadIdx.x;
    int rg = tid >> 4, cg = tid & 15;

    int pid[4];
#pragma unroll
    for (int i = 0; i < 4; i++) {
        int rr = 4 * rg + i;
        pid[i] = (rr < nr) ? g_list[r * LCAP + row0 + rr] : -1;
    }
#pragma unroll
    for (int p = 0; p < 4; p++) {
        int idx = tid + 256 * p;
        int rr = idx >> 4, ku = idx & 15;
        int pp = g_list[r * LCAP + row0 + ((rr < nr) ? rr : 0)];
        *(float4*)(As + rr * 64 + 4 * ku) = *(const float4*)(g_xu + pp * HN + 4 * ku);
    }
    float rowm[4] = {-3.4e38f, -3.4e38f, -3.4e38f, -3.4e38f};

    for (int ct = 0; ct < 8; ct++) {
        __syncthreads();
#pragma unroll
        for (int p = 0; p < 8; p++) {
            int idx = tid + 256 * p;
            int c = idx >> 4, ku = idx & 15;
            *(float4*)(Bs + c * 64 + 4 * (ku ^ (c >> 3))) =
                *(const float4*)(g_ev + (r * EN + ct * 128 + c) * HN + 4 * ku);
        }
        __syncthreads();

        unsigned long long acc[4][8];
#pragma unroll
        for (int i = 0; i < 4; i++)
#pragma unroll
            for (int j = 0; j < 8; j++) acc[i][j] = 0ull;
#pragma unroll
        for (int ks = 0; ks < 16; ks++) {
            ulonglong2 a2[4], b2[8];
#pragma unroll
            for (int i = 0; i < 4; i++)
                a2[i] = *(const ulonglong2*)(As + (4 * rg + i) * 64 + 4 * ks);
#pragma unroll
            for (int j = 0; j < 8; j++)
                b2[j] = *(const ulonglong2*)(Bs + (8 * cg + j) * 64 + 4 * (ks ^ cg));
#pragma unroll
            for (int i = 0; i < 4; i++)
#pragma unroll
                for (int j = 0; j < 8; j++) {
                    acc[i][j] = ffma2(a2[i].x, b2[j].x, acc[i][j]);
                    acc[i][j] = ffma2(a2[i].y, b2[j].y, acc[i][j]);
                }
        }
#pragma unroll
        for (int i = 0; i < 4; i++) {
            if (pid[i] >= 0) {
                float s[8];
#pragma unroll
                for (int j = 0; j < 8; j++) {
                    s[j] = psum(acc[i][j]);
                    rowm[i] = fmaxf(rowm[i], s[j]);
                }
                float* dp = g_scores + pid[i] * EN + ct * 128 + 8 * cg;
                *(float4*)dp = make_float4(s[0], s[1], s[2], s[3]);
                *(float4*)(dp + 4) = make_float4(s[4], s[5], s[6], s[7]);
            }
        }
    }
#pragma unroll
    for (int i = 0; i < 4; i++) {
        float m = rowm[i];
        m = fmaxf(m, __shfl_xor_sync(0xffffffffu, m, 1));
        m = fmaxf(m, __shfl_xor_sync(0xffffffffu, m, 2));
        m = fmaxf(m, __shfl_xor_sync(0xffffffffu, m, 4));
        m = fmaxf(m, __shfl_xor_sync(0xffffffffu, m, 8));
        if (cg == 0 && pid[i] >= 0) g_rowm[pid[i]] = m;
    }
}

// sample: 2-pass register pipeline
__global__ __launch_bounds__(256) void sample_kernel(const float* __restrict__ rnd,
                                                     float* __restrict__ out) {
    __shared__ float sred0[8], sred1[8], swt[8];
    __shared__ int selS;
    int b = blockIdx.x, tid = threadIdx.x, lane = tid & 31, warp = tid >> 5;

    float m0 = g_rowm[2 * b], m1 = g_rowm[2 * b + 1];
    float4 f0 = *(const float4*)(g_scores + (size_t)(2 * b) * EN + 4 * tid);
    float4 f1 = *(const float4*)(g_scores + (size_t)(2 * b + 1) * EN + 4 * tid);
    float e0[4] = {__expf(f0.x - m0), __expf(f0.y - m0), __expf(f0.z - m0), __expf(f0.w - m0)};
    float e1[4] = {__expf(f1.x - m1), __expf(f1.y - m1), __expf(f1.z - m1), __expf(f1.w - m1)};
    float z0 = e0[0] + e0[1] + e0[2] + e0[3];
    float z1 = e1[0] + e1[1] + e1[2] + e1[3];
#pragma unroll
    for (int off = 16; off > 0; off >>= 1) {
        z0 += __shfl_down_sync(0xffffffffu, z0, off);
        z1 += __shfl_down_sync(0xffffffffu, z1, off);
    }
    if (lane == 0) { sred0[warp] = z0; sred1[warp] = z1; }
    if (tid == 0) selS = EN;
    __syncthreads();
    float Z0 = 0.f, Z1 = 0.f;
#pragma unroll
    for (int w = 0; w < 8; w++) { Z0 += sred0[w]; Z1 += sred1[w]; }
    float c0 = g_topw[2 * b] / Z0, c1 = g_topw[2 * b + 1] / Z1;
    float rea[4];
#pragma unroll
    for (int i = 0; i < 4; i++) rea[i] = c0 * e0[i] + c1 * e1[i];

    float q0 = rea[0], q1 = q0 + rea[1], q2 = q1 + rea[2], q3 = q2 + rea[3];
    float t = q3, vsc = t;
#pragma unroll
    for (int off = 1; off < 32; off <<= 1) {
        float u = __shfl_up_sync(0xffffffffu, vsc, off);
        if (lane >= off) vsc += u;
    }
    if (lane == 31) swt[warp] = vsc;
    __syncthreads();
    if (warp == 0) {
        float w = (lane < 8) ? swt[lane] : 0.f;
#pragma unroll
        for (int off = 1; off < 8; off <<= 1) {
            float u = __shfl_up_sync(0xffffffffu, w, off);
            if (lane >= off) w += u;
        }
        if (lane < 8) swt[lane] = w;
    }
    __syncthreads();
    float base = (warp ? swt[warp - 1] : 0.f) + (vsc - t);
    float cum[4] = {base + q0, base + q1, base + q2, base + q3};

    float rv = rnd[b];
    int cand = EN;
#pragma unroll
    for (int i = 0; i < 4; i++) {
        if (cum[i] > rv) { cand = 4 * tid + i; break; }
    }
    if (cand < EN) atomicMin(&selS, cand);
    __syncthreads();
    int sel = selS;
    if (sel == EN) {
        if (tid == 0) { out[b] = 0.f; out[BN + b] = logf(rea[0]); }
    } else if (tid == (sel >> 2)) {
        out[b] = (float)sel;
        out[BN + b] = logf(rea[sel & 3]);
    }
}

__global__ __launch_bounds__(256) void finish_kernel(float* __restrict__ out) {
    __shared__ float red[16][16];
    __shared__ float col[16];
    int tid = threadIdx.x;
    int c = tid & 15, seg = tid >> 4;
    float s = 0.f;
    for (int bk = seg * 64; bk < seg * 64 + 64; bk++) s += g_auxp[bk * 16 + c];
    red[c][seg] = s;
    __syncthreads();
    if (tid < 16) {
        float t = 0.f;
        for (int q = 0; q < 16; q++) t += red[tid][q];
        col[tid] = t;
    }
    __syncthreads();
    if (tid == 0) {
        float s2 = 0.f;
        for (int r = 0; r < RN; r++)
            s2 += (col[r] / (float)BN) * (col[8 + r] / (float)BN);
        out[2 * BN] = (float)RN * s2 * 0.05f;
    }
}

extern "C" void kernel_launch(void* const* d_in, const int* in_sizes, int n_in,
                              void* d_out, int out_size) {
    const float* x   = (const float*)d_in[0];
    const float* re  = (const float*)d_in[1];
    const float* rnd = (const float*)d_in[2];
    const float* gw  = (const float*)d_in[3];
    const float* gb  = (const float*)d_in[4];
    const float* Uw  = (const float*)d_in[5];
    const float* Ub  = (const float*)d_in[6];
    const float* Vw  = (const float*)d_in[7];
    const float* Vb  = (const float*)d_in[8];
    float* out = (float*)d_out;

    init_kernel<<<1, 32>>>();
    prep_kernel<<<dim3(RN, 2, DN / 32), 256>>>(Uw, Vw);
    gate_kernel<<<GATE_BLOCKS, 256>>>(x, gw, gb);
    proj_kernel<false><<<dim3(RN, EN / 64), 128>>>(re, Vb);
    proj_kernel<true><<<dim3(RN, 2 * BN / 64), 128>>>(x, Ub);
    score_kernel<<<dim3(RN, 2 * BN / 64), 256>>>();
    sample_kernel<<<BN, 256>>>(rnd, out);
    finish_kernel<<<1, 256>>>(out);
}

// round 6
// speedup vs baseline: 2.1087x; 1.1260x over previous
#include <cuda_runtime.h>
#include <math.h>

#define BN 8192
#define DN 384
#define RN 8
#define HN 64
#define EN 1024
#define GATE_BLOCKS (BN/8)
#define LCAP (2*BN)
#define EVT (EN/64)          // 16 ev tiles per router
#define XUT (2*BN/64)        // 256 xu tiles per router

__device__ float g_xu[2*BN*HN];
__device__ float g_scores[2*BN*EN];
__device__ float g_ev[RN*EN*HN];
__device__ float g_UwT[RN*HN*DN];
__device__ float g_VwT[RN*HN*DN];
__device__ float g_rowm[2*BN];
__device__ float g_topw[2*BN];
__device__ int   g_cnt[RN];
__device__ int   g_list[RN*LCAP];
__device__ float g_auxp[GATE_BLOCKS*16];

__device__ __forceinline__ unsigned long long ffma2(unsigned long long a,
                                                    unsigned long long b,
                                                    unsigned long long c) {
    unsigned long long d;
    asm("fma.rn.f32x2 %0,%1,%2,%3;" : "=l"(d) : "l"(a), "l"(b), "l"(c));
    return d;
}
__device__ __forceinline__ float psum(unsigned long long v) {
    float lo, hi;
    asm("mov.b64 {%0,%1},%2;" : "=f"(lo), "=f"(hi) : "l"(v));
    return lo + hi;
}

__global__ void init_kernel() {
    if (threadIdx.x < RN) g_cnt[threadIdx.x] = 0;
}

// transpose Uw/Vw -> [r][h][d]
__global__ __launch_bounds__(256) void prep_kernel(const float* __restrict__ Uw,
                                                   const float* __restrict__ Vw) {
    __shared__ float t[32][65];
    int r = blockIdx.x, m = blockIdx.y, d0 = blockIdx.z * 32, tid = threadIdx.x;
    const float* in = (m ? Vw : Uw) + r * DN * HN;
    float* outp = (m ? g_VwT : g_UwT) + r * HN * DN;
    for (int idx = tid; idx < 32 * 64; idx += 256) {
        int dd = idx >> 6, h = idx & 63;
        t[dd][h] = in[(d0 + dd) * HN + h];
    }
    __syncthreads();
    for (int idx = tid; idx < 64 * 32; idx += 256) {
        int h = idx >> 5, dd = idx & 31;
        outp[h * DN + d0 + dd] = t[dd][h];
    }
}

__global__ __launch_bounds__(256) void gate_kernel(const float* __restrict__ x,
                                                   const float* __restrict__ gw,
                                                   const float* __restrict__ gb) {
    __shared__ float warpAux[8][16];
    int tid = threadIdx.x, warp = tid >> 5, lane = tid & 31;
    int b = blockIdx.x * 8 + warp;
    float acc[RN];
#pragma unroll
    for (int r = 0; r < RN; r++) acc[r] = 0.f;
    const float* xb = x + b * DN;
#pragma unroll 4
    for (int i = 0; i < DN / 32; i++) {
        int d = lane + 32 * i;
        float xv = xb[d];
        const float4* g4 = reinterpret_cast<const float4*>(gw + d * RN);
        float4 w0 = g4[0], w1 = g4[1];
        acc[0] += xv * w0.x; acc[1] += xv * w0.y; acc[2] += xv * w0.z; acc[3] += xv * w0.w;
        acc[4] += xv * w1.x; acc[5] += xv * w1.y; acc[6] += xv * w1.z; acc[7] += xv * w1.w;
    }
#pragma unroll
    for (int r = 0; r < RN; r++)
#pragma unroll
        for (int off = 16; off > 0; off >>= 1)
            acc[r] += __shfl_down_sync(0xffffffffu, acc[r], off);

    if (lane == 0) {
        float lg[RN]; float m = -3.4e38f;
#pragma unroll
        for (int r = 0; r < RN; r++) { lg[r] = acc[r] + gb[r]; m = fmaxf(m, lg[r]); }
        float Z = 0.f, pr[RN];
#pragma unroll
        for (int r = 0; r < RN; r++) { pr[r] = __expf(lg[r] - m); Z += pr[r]; }
        float invZ = 1.f / Z;
        int i0 = 0; float v0 = lg[0];
        int i1 = -1; float v1 = -3.4e38f;
#pragma unroll
        for (int r = 1; r < RN; r++) {
            if (lg[r] > v0) { i1 = i0; v1 = v0; i0 = r; v0 = lg[r]; }
            else if (lg[r] > v1) { i1 = r; v1 = lg[r]; }
        }
        float e1 = __expf(v1 - v0);
        float w0 = 1.f / (1.f + e1), w1 = e1 / (1.f + e1);
        g_topw[2 * b] = w0; g_topw[2 * b + 1] = w1;
        int s0 = atomicAdd(&g_cnt[i0], 1); g_list[i0 * LCAP + s0] = 2 * b;
        int s1 = atomicAdd(&g_cnt[i1], 1); g_list[i1 * LCAP + s1] = 2 * b + 1;
#pragma unroll
        for (int r = 0; r < RN; r++) {
            warpAux[warp][r] = pr[r] * invZ;
            warpAux[warp][8 + r] = (r == i0 || r == i1) ? 1.f : 0.f;
        }
    }
    __syncthreads();
    if (tid < 16) {
        float s = 0.f;
        for (int w = 0; w < 8; w++) s += warpAux[w][tid];
        g_auxp[blockIdx.x * 16 + tid] = s;
    }
}

// merged proj GEMM: y<EVT -> ev tile (re@Vw -> g_ev), else gathered xu tile (x@Uw -> g_xu)
__global__ __launch_bounds__(128) void proj_kernel(const float* __restrict__ x,
                                                   const float* __restrict__ re,
                                                   const float* __restrict__ Ub,
                                                   const float* __restrict__ Vb) {
    __shared__ __align__(16) float As[64 * 32];
    __shared__ __align__(16) float Bs[64 * 32];
    __shared__ int pairS[64];
    int r = blockIdx.x, y = blockIdx.y, tid = threadIdx.x;
    bool gather = (y >= EVT);
    int row0, nr = 64;
    const float* X; const float* bias; const float* WT;
    if (gather) {
        int n = g_cnt[r];
        row0 = (y - EVT) * 64;
        if (row0 >= n) return;
        nr = min(64, n - row0);
        if (tid < 64) pairS[tid] = g_list[r * LCAP + row0 + ((tid < nr) ? tid : 0)];
        __syncthreads();
        X = x; bias = Ub; WT = g_UwT + r * HN * DN;
    } else {
        row0 = y * 64;
        X = re; bias = Vb; WT = g_VwT + r * HN * DN;
    }
    int rg = tid >> 3, cg = tid & 7;

    unsigned long long acc[4][8];
#pragma unroll
    for (int i = 0; i < 4; i++)
#pragma unroll
        for (int j = 0; j < 8; j++) acc[i][j] = 0ull;

    for (int kt = 0; kt < DN / 32; kt++) {
        int k0 = kt * 32;
#pragma unroll
        for (int p = 0; p < 4; p++) {
            int idx = tid + 128 * p;
            int rr = idx >> 3, ku = idx & 7;
            const float* src = gather ? X + (pairS[rr] >> 1) * DN + k0 + 4 * ku
                                      : X + (row0 + rr) * DN + k0 + 4 * ku;
            *(float4*)(As + rr * 32 + 4 * ku) = *(const float4*)src;
        }
#pragma unroll
        for (int p = 0; p < 4; p++) {
            int idx = tid + 128 * p;
            int c = idx >> 3, ku = idx & 7;
            *(float4*)(Bs + c * 32 + 4 * (ku ^ (c >> 3))) =
                *(const float4*)(WT + c * DN + k0 + 4 * ku);
        }
        __syncthreads();
#pragma unroll
        for (int ks = 0; ks < 8; ks++) {
            ulonglong2 a2[4], b2[8];
#pragma unroll
            for (int i = 0; i < 4; i++)
                a2[i] = *(const ulonglong2*)(As + (4 * rg + i) * 32 + 4 * ks);
#pragma unroll
            for (int j = 0; j < 8; j++)
                b2[j] = *(const ulonglong2*)(Bs + (8 * cg + j) * 32 + 4 * (ks ^ cg));
#pragma unroll
            for (int i = 0; i < 4; i++)
#pragma unroll
                for (int j = 0; j < 8; j++) {
                    acc[i][j] = ffma2(a2[i].x, b2[j].x, acc[i][j]);
                    acc[i][j] = ffma2(a2[i].y, b2[j].y, acc[i][j]);
                }
        }
        __syncthreads();
    }
#pragma unroll
    for (int i = 0; i < 4; i++) {
        int row = 4 * rg + i;
        float vv[8]; float ssq = 0.f;
#pragma unroll
        for (int j = 0; j < 8; j++) {
            vv[j] = psum(acc[i][j]) + bias[r * HN + 8 * cg + j];
            ssq += vv[j] * vv[j];
        }
        ssq += __shfl_xor_sync(0xffffffffu, ssq, 1);
        ssq += __shfl_xor_sync(0xffffffffu, ssq, 2);
        ssq += __shfl_xor_sync(0xffffffffu, ssq, 4);
        float inv = 1.f / fmaxf(sqrtf(ssq), 1e-12f);
        float* dst;
        if (gather) {
            if (row >= nr) continue;
            dst = g_xu + pairS[row] * HN + 8 * cg;
        } else {
            dst = g_ev + (r * EN + row0 + row) * HN + 8 * cg;
        }
        *(float4*)dst = make_float4(vv[0] * inv, vv[1] * inv, vv[2] * inv, vv[3] * inv);
        *(float4*)(dst + 4) = make_float4(vv[4] * inv, vv[5] * inv, vv[6] * inv, vv[7] * inv);
    }
}

// score GEMM: 32 rows x 1024 cols per block (128 thr), K=64, FFMA2 + row max
__global__ __launch_bounds__(128) void score_kernel() {
    __shared__ __align__(16) float As[32 * 64];
    __shared__ __align__(16) float Bs[128 * 64];
    int r = blockIdx.x;
    int n = g_cnt[r];
    int row0 = blockIdx.y * 32;
    if (row0 >= n) return;
    int nr = min(32, n - row0);
    int tid = threadIdx.x;
    int rg = tid >> 4, cg = tid & 15;   // 8 row-groups x 16 col-groups

    int pid[4];
#pragma unroll
    for (int i = 0; i < 4; i++) {
        int rr = 4 * rg + i;
        pid[i] = (rr < nr) ? g_list[r * LCAP + row0 + rr] : -1;
    }
#pragma unroll
    for (int p = 0; p < 4; p++) {
        int idx = tid + 128 * p;
        int rr = idx >> 4, ku = idx & 15;
        int pp = g_list[r * LCAP + row0 + ((rr < nr) ? rr : 0)];
        *(float4*)(As + rr * 64 + 4 * ku) = *(const float4*)(g_xu + pp * HN + 4 * ku);
    }
    float rowm[4] = {-3.4e38f, -3.4e38f, -3.4e38f, -3.4e38f};

    for (int ct = 0; ct < 8; ct++) {
        __syncthreads();
#pragma unroll
        for (int p = 0; p < 16; p++) {
            int idx = tid + 128 * p;
            int c = idx >> 4, ku = idx & 15;
            *(float4*)(Bs + c * 64 + 4 * (ku ^ (c >> 3))) =
                *(const float4*)(g_ev + (r * EN + ct * 128 + c) * HN + 4 * ku);
        }
        __syncthreads();

        unsigned long long acc[4][8];
#pragma unroll
        for (int i = 0; i < 4; i++)
#pragma unroll
            for (int j = 0; j < 8; j++) acc[i][j] = 0ull;
#pragma unroll
        for (int ks = 0; ks < 16; ks++) {
            ulonglong2 a2[4], b2[8];
#pragma unroll
            for (int i = 0; i < 4; i++)
                a2[i] = *(const ulonglong2*)(As + (4 * rg + i) * 64 + 4 * ks);
#pragma unroll
            for (int j = 0; j < 8; j++)
                b2[j] = *(const ulonglong2*)(Bs + (8 * cg + j) * 64 + 4 * (ks ^ cg));
#pragma unroll
            for (int i = 0; i < 4; i++)
#pragma unroll
                for (int j = 0; j < 8; j++) {
                    acc[i][j] = ffma2(a2[i].x, b2[j].x, acc[i][j]);
                    acc[i][j] = ffma2(a2[i].y, b2[j].y, acc[i][j]);
                }
        }
#pragma unroll
        for (int i = 0; i < 4; i++) {
            if (pid[i] >= 0) {
                float s[8];
#pragma unroll
                for (int j = 0; j < 8; j++) {
                    s[j] = psum(acc[i][j]);
                    rowm[i] = fmaxf(rowm[i], s[j]);
                }
                float* dp = g_scores + pid[i] * EN + ct * 128 + 8 * cg;
                *(float4*)dp = make_float4(s[0], s[1], s[2], s[3]);
                *(float4*)(dp + 4) = make_float4(s[4], s[5], s[6], s[7]);
            }
        }
    }
#pragma unroll
    for (int i = 0; i < 4; i++) {
        float m = rowm[i];
        m = fmaxf(m, __shfl_xor_sync(0xffffffffu, m, 1));
        m = fmaxf(m, __shfl_xor_sync(0xffffffffu, m, 2));
        m = fmaxf(m, __shfl_xor_sync(0xffffffffu, m, 4));
        m = fmaxf(m, __shfl_xor_sync(0xffffffffu, m, 8));
        if (cg == 0 && pid[i] >= 0) g_rowm[pid[i]] = m;
    }
}

// sample: 2-pass register pipeline
__global__ __launch_bounds__(256) void sample_kernel(const float* __restrict__ rnd,
                                                     float* __restrict__ out) {
    __shared__ float sred0[8], sred1[8], swt[8];
    __shared__ int selS;
    int b = blockIdx.x, tid = threadIdx.x, lane = tid & 31, warp = tid >> 5;

    float m0 = g_rowm[2 * b], m1 = g_rowm[2 * b + 1];
    float4 f0 = *(const float4*)(g_scores + (size_t)(2 * b) * EN + 4 * tid);
    float4 f1 = *(const float4*)(g_scores + (size_t)(2 * b + 1) * EN + 4 * tid);
    float e0[4] = {__expf(f0.x - m0), __expf(f0.y - m0), __expf(f0.z - m0), __expf(f0.w - m0)};
    float e1[4] = {__expf(f1.x - m1), __expf(f1.y - m1), __expf(f1.z - m1), __expf(f1.w - m1)};
    float z0 = e0[0] + e0[1] + e0[2] + e0[3];
    float z1 = e1[0] + e1[1] + e1[2] + e1[3];
#pragma unroll
    for (int off = 16; off > 0; off >>= 1) {
        z0 += __shfl_down_sync(0xffffffffu, z0, off);
        z1 += __shfl_down_sync(0xffffffffu, z1, off);
    }
    if (lane == 0) { sred0[warp] = z0; sred1[warp] = z1; }
    if (tid == 0) selS = EN;
    __syncthreads();
    float Z0 = 0.f, Z1 = 0.f;
#pragma unroll
    for (int w = 0; w < 8; w++) { Z0 += sred0[w]; Z1 += sred1[w]; }
    float c0 = g_topw[2 * b] / Z0, c1 = g_topw[2 * b + 1] / Z1;
    float rea[4];
#pragma unroll
    for (int i = 0; i < 4; i++) rea[i] = c0 * e0[i] + c1 * e1[i];

    float q0 = rea[0], q1 = q0 + rea[1], q2 = q1 + rea[2], q3 = q2 + rea[3];
    float t = q3, vsc = t;
#pragma unroll
    for (int off = 1; off < 32; off <<= 1) {
        float u = __shfl_up_sync(0xffffffffu, vsc, off);
        if (lane >= off) vsc += u;
    }
    if (lane == 31) swt[warp] = vsc;
    __syncthreads();
    if (warp == 0) {
        float w = (lane < 8) ? swt[lane] : 0.f;
#pragma unroll
        for (int off = 1; off < 8; off <<= 1) {
            float u = __shfl_up_sync(0xffffffffu, w, off);
            if (lane >= off) w += u;
        }
        if (lane < 8) swt[lane] = w;
    }
    __syncthreads();
    float base = (warp ? swt[warp - 1] : 0.f) + (vsc - t);
    float cum[4] = {base + q0, base + q1, base + q2, base + q3};

    float rv = rnd[b];
    int cand = EN;
#pragma unroll
    for (int i = 0; i < 4; i++) {
        if (cum[i] > rv) { cand = 4 * tid + i; break; }
    }
    if (cand < EN) atomicMin(&selS, cand);
    __syncthreads();
    int sel = selS;
    if (sel == EN) {
        if (tid == 0) { out[b] = 0.f; out[BN + b] = logf(rea[0]); }
    } else if (tid == (sel >> 2)) {
        out[b] = (float)sel;
        out[BN + b] = logf(rea[sel & 3]);
    }
}

__global__ __launch_bounds__(256) void finish_kernel(float* __restrict__ out) {
    __shared__ float red[16][16];
    __shared__ float col[16];
    int tid = threadIdx.x;
    int c = tid & 15, seg = tid >> 4;
    float s = 0.f;
    for (int bk = seg * 64; bk < seg * 64 + 64; bk++) s += g_auxp[bk * 16 + c];
    red[c][seg] = s;
    __syncthreads();
    if (tid < 16) {
        float t = 0.f;
        for (int q = 0; q < 16; q++) t += red[tid][q];
        col[tid] = t;
    }
    __syncthreads();
    if (tid == 0) {
        float s2 = 0.f;
        for (int r = 0; r < RN; r++)
            s2 += (col[r] / (float)BN) * (col[8 + r] / (float)BN);
        out[2 * BN] = (float)RN * s2 * 0.05f;
    }
}

extern "C" void kernel_launch(void* const* d_in, const int* in_sizes, int n_in,
                              void* d_out, int out_size) {
    const float* x   = (const float*)d_in[0];
    const float* re  = (const float*)d_in[1];
    const float* rnd = (const float*)d_in[2];
    const float* gw  = (const float*)d_in[3];
    const float* gb  = (const float*)d_in[4];
    const float* Uw  = (const float*)d_in[5];
    const float* Ub  = (const float*)d_in[6];
    const float* Vw  = (const float*)d_in[7];
    const float* Vb  = (const float*)d_in[8];
    float* out = (float*)d_out;

    init_kernel<<<1, 32>>>();
    prep_kernel<<<dim3(RN, 2, DN / 32), 256>>>(Uw, Vw);
    gate_kernel<<<GATE_BLOCKS, 256>>>(x, gw, gb);
    proj_kernel<<<dim3(RN, EVT + XUT), 128>>>(x, re, Ub, Vb);
    score_kernel<<<dim3(RN, 2 * BN / 32), 128>>>();
    sample_kernel<<<BN, 256>>>(rnd, out);
    finish_kernel<<<1, 256>>>(out);
}

// round 9
// speedup vs baseline: 2.3844x; 1.1308x over previous
#include <cuda_runtime.h>
#include <cstdint>
#include <math.h>

#define BN 8192
#define DN 384
#define RN 8
#define HN 64
#define EN 1024
#define GATE_BLOCKS (BN/8)
#define LCAP (2*BN)
#define EVT (EN/64)
#define XUT (2*BN/64)

__device__ float g_xu[2*BN*HN];
__device__ float g_scores[2*BN*EN];   // holds exp(score)
__device__ float g_ev[RN*EN*HN];
__device__ float g_UwT[RN*HN*DN];
__device__ float g_VwT[RN*HN*DN];
__device__ float g_rowz[2*BN];        // per-pair sum of exp
__device__ float g_topw[2*BN];
__device__ int   g_cnt[RN];
__device__ int   g_list[RN*LCAP];
__device__ float g_auxp[GATE_BLOCKS*16];

__device__ __forceinline__ unsigned long long ffma2(unsigned long long a,
                                                    unsigned long long b,
                                                    unsigned long long c) {
    unsigned long long d;
    asm("fma.rn.f32x2 %0,%1,%2,%3;" : "=l"(d) : "l"(a), "l"(b), "l"(c));
    return d;
}
__device__ __forceinline__ float psum(unsigned long long v) {
    float lo, hi;
    asm("mov.b64 {%0,%1},%2;" : "=f"(lo), "=f"(hi) : "l"(v));
    return lo + hi;
}
__device__ __forceinline__ void cpa16(unsigned int dst, const void* src) {
    asm volatile("cp.async.cg.shared.global [%0],[%1],16;" :: "r"(dst), "l"(src));
}
#define CP_COMMIT() asm volatile("cp.async.commit_group;")
#define CP_WAIT(n)  asm volatile("cp.async.wait_group %0;" :: "n"(n))

// transpose Uw/Vw -> [r][h][d]; block (0,0,0) also zeroes g_cnt
__global__ __launch_bounds__(256) void prep_kernel(const float* __restrict__ Uw,
                                                   const float* __restrict__ Vw) {
    __shared__ float t[32][65];
    int r = blockIdx.x, m = blockIdx.y, d0 = blockIdx.z * 32, tid = threadIdx.x;
    if (blockIdx.x == 0 && blockIdx.y == 0 && blockIdx.z == 0 && tid < RN) g_cnt[tid] = 0;
    const float* in = (m ? Vw : Uw) + r * DN * HN;
    float* outp = (m ? g_VwT : g_UwT) + r * HN * DN;
    for (int idx = tid; idx < 32 * 64; idx += 256) {
        int dd = idx >> 6, h = idx & 63;
        t[dd][h] = in[(d0 + dd) * HN + h];
    }
    __syncthreads();
    for (int idx = tid; idx < 64 * 32; idx += 256) {
        int h = idx >> 5, dd = idx & 31;
        outp[h * DN + d0 + dd] = t[dd][h];
    }
}

__global__ __launch_bounds__(256) void gate_kernel(const float* __restrict__ x,
                                                   const float* __restrict__ gw,
                                                   const float* __restrict__ gb) {
    __shared__ float warpAux[8][16];
    int tid = threadIdx.x, warp = tid >> 5, lane = tid & 31;
    int b = blockIdx.x * 8 + warp;
    float acc[RN];
#pragma unroll
    for (int r = 0; r < RN; r++) acc[r] = 0.f;
    const float* xb = x + b * DN;
#pragma unroll 4
    for (int i = 0; i < DN / 32; i++) {
        int d = lane + 32 * i;
        float xv = xb[d];
        const float4* g4 = reinterpret_cast<const float4*>(gw + d * RN);
        float4 w0 = g4[0], w1 = g4[1];
        acc[0] += xv * w0.x; acc[1] += xv * w0.y; acc[2] += xv * w0.z; acc[3] += xv * w0.w;
        acc[4] += xv * w1.x; acc[5] += xv * w1.y; acc[6] += xv * w1.z; acc[7] += xv * w1.w;
    }
#pragma unroll
    for (int r = 0; r < RN; r++)
#pragma unroll
        for (int off = 16; off > 0; off >>= 1)
            acc[r] += __shfl_down_sync(0xffffffffu, acc[r], off);

    if (lane == 0) {
        float lg[RN]; float m = -3.4e38f;
#pragma unroll
        for (int r = 0; r < RN; r++) { lg[r] = acc[r] + gb[r]; m = fmaxf(m, lg[r]); }
        float Z = 0.f, pr[RN];
#pragma unroll
        for (int r = 0; r < RN; r++) { pr[r] = __expf(lg[r] - m); Z += pr[r]; }
        float invZ = 1.f / Z;
        int i0 = 0; float v0 = lg[0];
        int i1 = -1; float v1 = -3.4e38f;
#pragma unroll
        for (int r = 1; r < RN; r++) {
            if (lg[r] > v0) { i1 = i0; v1 = v0; i0 = r; v0 = lg[r]; }
            else if (lg[r] > v1) { i1 = r; v1 = lg[r]; }
        }
        float e1 = __expf(v1 - v0);
        float w0 = 1.f / (1.f + e1), w1 = e1 / (1.f + e1);
        g_topw[2 * b] = w0; g_topw[2 * b + 1] = w1;
        int s0 = atomicAdd(&g_cnt[i0], 1); g_list[i0 * LCAP + s0] = 2 * b;
        int s1 = atomicAdd(&g_cnt[i1], 1); g_list[i1 * LCAP + s1] = 2 * b + 1;
#pragma unroll
        for (int r = 0; r < RN; r++) {
            warpAux[warp][r] = pr[r] * invZ;
            warpAux[warp][8 + r] = (r == i0 || r == i1) ? 1.f : 0.f;
        }
    }
    __syncthreads();
    if (tid < 16) {
        float s = 0.f;
        for (int w = 0; w < 8; w++) s += warpAux[w][tid];
        g_auxp[blockIdx.x * 16 + tid] = s;
    }
}

// merged proj GEMM with cp.async double buffering.
// y<EVT -> ev tile (re@Vw -> g_ev), else gathered xu tile (x@Uw -> g_xu)
__global__ __launch_bounds__(128) void proj_kernel(const float* __restrict__ x,
                                                   const float* __restrict__ re,
                                                   const float* __restrict__ Ub,
                                                   const float* __restrict__ Vb) {
    __shared__ __align__(16) float As[2][64 * 32];
    __shared__ __align__(16) float Bs[2][64 * 32];
    __shared__ int pairS[64];
    int r = blockIdx.x, y = blockIdx.y, tid = threadIdx.x;
    bool gather = (y >= EVT);
    int row0, nr = 64;
    const float* X; const float* bias; const float* WT;
    if (gather) {
        int n = g_cnt[r];
        row0 = (y - EVT) * 64;
        if (row0 >= n) return;
        nr = min(64, n - row0);
        if (tid < 64) pairS[tid] = g_list[r * LCAP + row0 + ((tid < nr) ? tid : 0)];
        __syncthreads();
        X = x; bias = Ub; WT = g_UwT + r * HN * DN;
    } else {
        row0 = y * 64;
        X = re; bias = Vb; WT = g_VwT + r * HN * DN;
    }
    int rg = tid >> 3, cg = tid & 7;
    int ku = tid & 7;

    const float* asrc[4]; const float* bsrc[4];
    unsigned int adst[4][2], bdst[4][2];
#pragma unroll
    for (int p = 0; p < 4; p++) {
        int rr = (tid >> 3) + 16 * p;
        asrc[p] = gather ? X + (pairS[rr] >> 1) * DN + 4 * ku
                         : X + (row0 + rr) * DN + 4 * ku;
        bsrc[p] = WT + rr * DN + 4 * ku;
#pragma unroll
        for (int bf = 0; bf < 2; bf++) {
            adst[p][bf] = (unsigned int)__cvta_generic_to_shared(
                &As[bf][rr * 32 + 4 * (ku ^ ((rr >> 2) & 7))]);
            bdst[p][bf] = (unsigned int)__cvta_generic_to_shared(
                &Bs[bf][rr * 32 + 4 * (ku ^ (rr >> 3))]);
        }
    }
#pragma unroll
    for (int p = 0; p < 4; p++) { cpa16(adst[p][0], asrc[p]); cpa16(bdst[p][0], bsrc[p]); }
    CP_COMMIT();

    unsigned long long acc[4][8];
#pragma unroll
    for (int i = 0; i < 4; i++)
#pragma unroll
        for (int j = 0; j < 8; j++) acc[i][j] = 0ull;

    for (int kt = 0; kt < 12; kt++) {
        if (kt < 11) {
            int bf = (kt + 1) & 1, k0 = (kt + 1) * 32;
#pragma unroll
            for (int p = 0; p < 4; p++) {
                cpa16(adst[p][bf], asrc[p] + k0);
                cpa16(bdst[p][bf], bsrc[p] + k0);
            }
            CP_COMMIT();
            CP_WAIT(1);
        } else {
            CP_WAIT(0);
        }
        __syncthreads();
        const float* Ab = As[kt & 1];
        const float* Bb = Bs[kt & 1];
#pragma unroll
        for (int ks = 0; ks < 8; ks++) {
            ulonglong2 a2[4], b2[8];
#pragma unroll
            for (int i = 0; i < 4; i++) {
                int rr = 4 * rg + i;
                a2[i] = *(const ulonglong2*)(Ab + rr * 32 + 4 * (ks ^ ((rr >> 2) & 7)));
            }
#pragma unroll
            for (int j = 0; j < 8; j++)
                b2[j] = *(const ulonglong2*)(Bb + (8 * cg + j) * 32 + 4 * (ks ^ cg));
#pragma unroll
            for (int i = 0; i < 4; i++)
#pragma unroll
                for (int j = 0; j < 8; j++) {
                    acc[i][j] = ffma2(a2[i].x, b2[j].x, acc[i][j]);
                    acc[i][j] = ffma2(a2[i].y, b2[j].y, acc[i][j]);
                }
        }
        __syncthreads();
    }
#pragma unroll
    for (int i = 0; i < 4; i++) {
        int row = 4 * rg + i;
        float vv[8]; float ssq = 0.f;
#pragma unroll
        for (int j = 0; j < 8; j++) {
            vv[j] = psum(acc[i][j]) + bias[r * HN + 8 * cg + j];
            ssq += vv[j] * vv[j];
        }
        ssq += __shfl_xor_sync(0xffffffffu, ssq, 1);
        ssq += __shfl_xor_sync(0xffffffffu, ssq, 2);
        ssq += __shfl_xor_sync(0xffffffffu, ssq, 4);
        float inv = 1.f / fmaxf(sqrtf(ssq), 1e-12f);
        float* dst;
        if (gather) {
            if (row >= nr) continue;
            dst = g_xu + pairS[row] * HN + 8 * cg;
        } else {
            dst = g_ev + (r * EN + row0 + row) * HN + 8 * cg;
        }
        *(float4*)dst = make_float4(vv[0] * inv, vv[1] * inv, vv[2] * inv, vv[3] * inv);
        *(float4*)(dst + 4) = make_float4(vv[4] * inv, vv[5] * inv, vv[6] * inv, vv[7] * inv);
    }
}

// score GEMM: 64 rows x 1024 cols per block (128 thr), K=64.
// Stores exp(score) (|score|<=1, no max needed) and per-row Z. B double-buffered.
__global__ __launch_bounds__(128) void score_kernel() {
    __shared__ __align__(16) float As[64 * 64];
    __shared__ __align__(16) float Bs[2][64 * 64];
    int r = blockIdx.x;
    int n = g_cnt[r];
    int row0 = blockIdx.y * 64;
    if (row0 >= n) return;
    int nr = min(64, n - row0);
    int tid = threadIdx.x;
    int rg = tid >> 3, cg = tid & 7;   // 16 row-groups x 8 col-groups

    const float* evr = g_ev + (size_t)r * EN * HN;
    unsigned int bdst[8][2]; const float* bsrc[8];
#pragma unroll
    for (int p = 0; p < 8; p++) {
        int idx = tid + 128 * p;
        int c = idx >> 4, k4 = idx & 15;
        bsrc[p] = evr + c * HN + 4 * k4;
#pragma unroll
        for (int bf = 0; bf < 2; bf++)
            bdst[p][bf] = (unsigned int)__cvta_generic_to_shared(
                &Bs[bf][c * 64 + 4 * (k4 ^ (c >> 3))]);
    }
#pragma unroll
    for (int p = 0; p < 8; p++) cpa16(bdst[p][0], bsrc[p]);
    CP_COMMIT();

    int pid[4];
#pragma unroll
    for (int i = 0; i < 4; i++) {
        int rr = 4 * rg + i;
        pid[i] = (rr < nr) ? g_list[r * LCAP + row0 + rr] : -1;
    }
#pragma unroll
    for (int p = 0; p < 8; p++) {
        int idx = tid + 128 * p;
        int rr = idx >> 4, k4 = idx & 15;
        int pp = g_list[r * LCAP + row0 + ((rr < nr) ? rr : 0)];
        *(float4*)(As + rr * 64 + 4 * (k4 ^ ((rr >> 2) & 7))) =
            *(const float4*)(g_xu + pp * HN + 4 * k4);
    }

    float rowZ[4] = {0.f, 0.f, 0.f, 0.f};

    for (int ct = 0; ct < 16; ct++) {
        if (ct < 15) {
            int bf = (ct + 1) & 1, off = (ct + 1) * 64 * HN;
#pragma unroll
            for (int p = 0; p < 8; p++) cpa16(bdst[p][bf], bsrc[p] + off);
            CP_COMMIT();
            CP_WAIT(1);
        } else {
            CP_WAIT(0);
        }
        __syncthreads();
        const float* Bb = Bs[ct & 1];

        unsigned long long acc[4][8];
#pragma unroll
        for (int i = 0; i < 4; i++)
#pragma unroll
            for (int j = 0; j < 8; j++) acc[i][j] = 0ull;
#pragma unroll
        for (int ks = 0; ks < 16; ks++) {
            ulonglong2 a2[4], b2[8];
#pragma unroll
            for (int i = 0; i < 4; i++) {
                int rr = 4 * rg + i;
                a2[i] = *(const ulonglong2*)(As + rr * 64 + 4 * (ks ^ ((rr >> 2) & 7)));
            }
#pragma unroll
            for (int j = 0; j < 8; j++)
                b2[j] = *(const ulonglong2*)(Bb + (8 * cg + j) * 64 + 4 * (ks ^ cg));
#pragma unroll
            for (int i = 0; i < 4; i++)
#pragma unroll
                for (int j = 0; j < 8; j++) {
                    acc[i][j] = ffma2(a2[i].x, b2[j].x, acc[i][j]);
                    acc[i][j] = ffma2(a2[i].y, b2[j].y, acc[i][j]);
                }
        }
#pragma unroll
        for (int i = 0; i < 4; i++) {
            if (pid[i] >= 0) {
                float e[8];
#pragma unroll
                for (int j = 0; j < 8; j++) {
                    e[j] = __expf(psum(acc[i][j]));
                    rowZ[i] += e[j];
                }
                float* dp = g_scores + (size_t)pid[i] * EN + ct * 64 + 8 * cg;
                *(float4*)dp = make_float4(e[0], e[1], e[2], e[3]);
                *(float4*)(dp + 4) = make_float4(e[4], e[5], e[6], e[7]);
            }
        }
        __syncthreads();
    }
#pragma unroll
    for (int i = 0; i < 4; i++) {
        float z = rowZ[i];
        z += __shfl_xor_sync(0xffffffffu, z, 1);
        z += __shfl_xor_sync(0xffffffffu, z, 2);
        z += __shfl_xor_sync(0xffffffffu, z, 4);
        if (cg == 0 && pid[i] >= 0) g_rowz[pid[i]] = z;
    }
}

// sample: combine + scan + inverse-CDF + log (scores already exp'd; Z precomputed)
// block 0 additionally computes the aux loss
__global__ __launch_bounds__(256) void sample_kernel(const float* __restrict__ rnd,
                                                     float* __restrict__ out) {
    __shared__ float swt[8];
    __shared__ int selS;
    __shared__ float red[16][17];
    int b = blockIdx.x, tid = threadIdx.x, lane = tid & 31, warp = tid >> 5;

    float c0 = g_topw[2 * b] / g_rowz[2 * b];
    float c1 = g_topw[2 * b + 1] / g_rowz[2 * b + 1];
    float4 f0 = *(const float4*)(g_scores + (size_t)(2 * b) * EN + 4 * tid);
    float4 f1 = *(const float4*)(g_scores + (size_t)(2 * b + 1) * EN + 4 * tid);
    float rea[4] = {c0 * f0.x + c1 * f1.x, c0 * f0.y + c1 * f1.y,
                    c0 * f0.z + c1 * f1.z, c0 * f0.w + c1 * f1.w};

    if (tid == 0) selS = EN;
    float q0 = rea[0], q1 = q0 + rea[1], q2 = q1 + rea[2], q3 = q2 + rea[3];
    float t = q3, vsc = t;
#pragma unroll
    for (int off = 1; off < 32; off <<= 1) {
        float u = __shfl_up_sync(0xffffffffu, vsc, off);
        if (lane >= off) vsc += u;
    }
    if (lane == 31) swt[warp] = vsc;
    __syncthreads();
    if (warp == 0) {
        float w = (lane < 8) ? swt[lane] : 0.f;
#pragma unroll
        for (int off = 1; off < 8; off <<= 1) {
            float u = __shfl_up_sync(0xffffffffu, w, off);
            if (lane >= off) w += u;
        }
        if (lane < 8) swt[lane] = w;
    }
    __syncthreads();
    float base = (warp ? swt[warp - 1] : 0.f) + (vsc - t);
    float cum[4] = {base + q0, base + q1, base + q2, base + q3};

    float rv = rnd[b];
    int cand = EN;
#pragma unroll
    for (int i = 0; i < 4; i++) {
        if (cum[i] > rv) { cand = 4 * tid + i; break; }
    }
    if (cand < EN) atomicMin(&selS, cand);
    __syncthreads();
    int sel = selS;
    if (sel == EN) {
        if (tid == 0) { out[b] = 0.f; out[BN + b] = logf(rea[0]); }
    } else if (tid == (sel >> 2)) {
        out[b] = (float)sel;
        out[BN + b] = logf(rea[sel & 3]);
    }

    if (b == 0) {
        int c = tid & 15, seg = tid >> 4;
        float s = 0.f;
        for (int bk = seg * 64; bk < seg * 64 + 64; bk++) s += g_auxp[bk * 16 + c];
        red[c][seg] = s;
        __syncthreads();
        if (tid == 0) {
            float col[16];
            for (int k = 0; k < 16; k++) {
                float tt = 0.f;
                for (int q = 0; q < 16; q++) tt += red[k][q];
                col[k] = tt;
            }
            float s2 = 0.f;
            for (int r = 0; r < RN; r++)
                s2 += (col[r] / (float)BN) * (col[8 + r] / (float)BN);
            out[2 * BN] = (float)RN * s2 * 0.05f;
        }
    }
}

extern "C" void kernel_launch(void* const* d_in, const int* in_sizes, int n_in,
                              void* d_out, int out_size) {
    const float* x   = (const float*)d_in[0];
    const float* re  = (const float*)d_in[1];
    const float* rnd = (const float*)d_in[2];
    const float* gw  = (const float*)d_in[3];
    const float* gb  = (const float*)d_in[4];
    const float* Uw  = (const float*)d_in[5];
    const float* Ub  = (const float*)d_in[6];
    const float* Vw  = (const float*)d_in[7];
    const float* Vb  = (const float*)d_in[8];
    float* out = (float*)d_out;

    prep_kernel<<<dim3(RN, 2, DN / 32), 256>>>(Uw, Vw);
    gate_kernel<<<GATE_BLOCKS, 256>>>(x, gw, gb);
    proj_kernel<<<dim3(RN, EVT + XUT), 128>>>(x, re, Ub, Vb);
    score_kernel<<<dim3(RN, 2 * BN / 64), 128>>>();
    sample_kernel<<<BN, 256>>>(rnd, out);
}